// round 2
// baseline (speedup 1.0000x reference)
#include <cuda_runtime.h>
#include <cuda_bf16.h>

#define N_BOND   100000
#define D        192
#define N_ETYPES 36
#define E_PER_T  30000
#define BATCH    256
#define N_EDGES  (N_ETYPES * E_PER_T)   // 1,080,000
#define N_SEG    (N_ETYPES * BATCH)     // 9216

// Scratch (no allocations allowed in kernel_launch)
__device__ float g_s[N_BOND];     // per-node scalar projection h[i,:] . W_out
__device__ float g_acc[N_SEG];    // segment accumulators, layout [type*BATCH + graph]

// ---------------------------------------------------------------------------
// Kernel 1: s[row] = dot(h[row, 0:192], W_out).  Warp per row, float4 loads.
// ---------------------------------------------------------------------------
__global__ void dot_kernel(const float* __restrict__ h,
                           const float* __restrict__ W) {
    const int lane  = threadIdx.x & 31;
    const int warp  = (blockIdx.x * blockDim.x + threadIdx.x) >> 5;
    const int nwarp = (gridDim.x * blockDim.x) >> 5;

    // W: 192 floats = 48 float4. lane holds W4[lane]; lanes 0..15 also W4[32+lane].
    const float4* W4 = reinterpret_cast<const float4*>(W);
    float4 w0 = W4[lane];
    float4 w1 = make_float4(0.f, 0.f, 0.f, 0.f);
    if (lane < 16) w1 = W4[32 + lane];

    for (int row = warp; row < N_BOND; row += nwarp) {
        const float4* h4 = reinterpret_cast<const float4*>(h + (size_t)row * D);
        float4 a = h4[lane];
        float acc = a.x * w0.x + a.y * w0.y + a.z * w0.z + a.w * w0.w;
        if (lane < 16) {
            float4 b = h4[32 + lane];
            acc += b.x * w1.x + b.y * w1.y + b.z * w1.z + b.w * w1.w;
        }
        #pragma unroll
        for (int off = 16; off > 0; off >>= 1)
            acc += __shfl_down_sync(0xffffffffu, acc, off);
        if (lane == 0) g_s[row] = acc;
    }
}

// ---------------------------------------------------------------------------
// Kernel 2: zero the accumulators (graph replay-safe: runs every launch)
// ---------------------------------------------------------------------------
__global__ void zero_kernel() {
    int i = blockIdx.x * blockDim.x + threadIdx.x;
    if (i < N_SEG) g_acc[i] = 0.f;
}

// ---------------------------------------------------------------------------
// Kernel 3: per-edge scalar gather + segmented warp reduction (keys sorted
// within each type, so equal keys are contiguous) + atomicAdd per run-head.
// ---------------------------------------------------------------------------
__global__ void edge_kernel(const int* __restrict__ src,
                            const int* __restrict__ seg) {
    const int idx  = blockIdx.x * blockDim.x + threadIdx.x;
    const int lane = threadIdx.x & 31;

    float val = 0.f;
    int   key = -1;
    if (idx < N_EDGES) {
        int t = idx / E_PER_T;            // edge type
        val = g_s[src[idx]];              // scalar gather, L2-resident (400 KB)
        key = t * BATCH + seg[idx];       // global segment id
    }

    // Segmented inclusive reduction over sorted keys within the warp.
    #pragma unroll
    for (int off = 1; off < 32; off <<= 1) {
        int   okey = __shfl_down_sync(0xffffffffu, key, off);
        float oval = __shfl_down_sync(0xffffffffu, val, off);
        if (lane + off < 32 && okey == key) val += oval;
    }
    int pkey = __shfl_up_sync(0xffffffffu, key, 1);
    bool head = (lane == 0) || (pkey != key);
    if (head && key >= 0) atomicAdd(&g_acc[key], val);
}

// ---------------------------------------------------------------------------
// Kernel 4: mask + softmax over the 36 types per graph. One thread per graph.
// mask is int32 (bool inputs are materialized as int32 by the harness).
// ---------------------------------------------------------------------------
__global__ void softmax_kernel(const int* __restrict__ mask,
                               float* __restrict__ out) {
    int b = blockIdx.x * blockDim.x + threadIdx.x;
    if (b >= BATCH) return;

    float v[N_ETYPES];
    float mx = -3.402823466e38f;
    #pragma unroll
    for (int t = 0; t < N_ETYPES; t++) {
        float x = g_acc[t * BATCH + b];
        if (mask[b * N_ETYPES + t] != 0) x = -1e9f;
        v[t] = x;
        mx = fmaxf(mx, x);
    }
    float s = 0.f;
    #pragma unroll
    for (int t = 0; t < N_ETYPES; t++) {
        v[t] = __expf(v[t] - mx);
        s += v[t];
    }
    float inv = 1.f / s;
    #pragma unroll
    for (int t = 0; t < N_ETYPES; t++)
        out[b * N_ETYPES + t] = v[t] * inv;
}

// ---------------------------------------------------------------------------
extern "C" void kernel_launch(void* const* d_in, const int* in_sizes, int n_in,
                              void* d_out, int out_size) {
    const float* h    = (const float*)d_in[0];   // [100000,192]
    const float* Wout = (const float*)d_in[1];   // [192,1]
    const int*   src  = (const int*)d_in[2];     // [36,30000]
    const int*   seg  = (const int*)d_in[3];     // [36,30000]
    const int*   mask = (const int*)d_in[4];     // [256,36] bool -> int32
    float*       out  = (float*)d_out;           // [256,36]

    zero_kernel<<<(N_SEG + 255) / 256, 256>>>();
    // 12500 blocks x 8 warps: one warp per row
    dot_kernel<<<(N_BOND + 7) / 8, 256>>>(h, Wout);
    edge_kernel<<<(N_EDGES + 255) / 256, 256>>>(src, seg);
    softmax_kernel<<<1, BATCH>>>(mask, out);
}

// round 3
// speedup vs baseline: 1.3667x; 1.3667x over previous
#include <cuda_runtime.h>
#include <cuda_bf16.h>

#define N_BOND   100000
#define D        192
#define N_ETYPES 36
#define E_PER_T  30000
#define BATCH    256
#define N_EDGES  (N_ETYPES * E_PER_T)   // 1,080,000
#define N_SEG    (N_ETYPES * BATCH)     // 9216

__device__ float g_s[N_BOND];     // per-node scalar projection h[i,:] . W_out
__device__ float g_acc[N_SEG];    // segment accumulators [type*BATCH + graph]

// ---------------------------------------------------------------------------
// Kernel 1: s[row] = dot(h[row,:], W_out). Warp per row, float4 loads.
// Also zeroes g_acc (fused to save a launch; completes before edge_kernel).
// ---------------------------------------------------------------------------
__global__ void dot_kernel(const float* __restrict__ h,
                           const float* __restrict__ W) {
    const int tid   = blockIdx.x * blockDim.x + threadIdx.x;
    if (tid < N_SEG) g_acc[tid] = 0.f;

    const int lane  = threadIdx.x & 31;
    const int warp  = tid >> 5;
    const int nwarp = (gridDim.x * blockDim.x) >> 5;

    const float4* W4 = reinterpret_cast<const float4*>(W);
    float4 w0 = W4[lane];
    float4 w1 = make_float4(0.f, 0.f, 0.f, 0.f);
    if (lane < 16) w1 = W4[32 + lane];

    for (int row = warp; row < N_BOND; row += nwarp) {
        const float4* h4 = reinterpret_cast<const float4*>(h + (size_t)row * D);
        float4 a = h4[lane];
        float acc = a.x * w0.x + a.y * w0.y + a.z * w0.z + a.w * w0.w;
        if (lane < 16) {
            float4 b = h4[32 + lane];
            acc += b.x * w1.x + b.y * w1.y + b.z * w1.z + b.w * w1.w;
        }
        #pragma unroll
        for (int off = 16; off > 0; off >>= 1)
            acc += __shfl_down_sync(0xffffffffu, acc, off);
        if (lane == 0) g_s[row] = acc;
    }
}

// ---------------------------------------------------------------------------
// Kernel 2: 4 edges per thread (int4), intra-thread run compaction, then
// warp-level segmented reduction over sorted keys, atomicAdd per run head.
// 4 | 30000 so a 4-pack never crosses a type boundary; key = t*256+seg is
// monotone nondecreasing across the whole edge array.
// ---------------------------------------------------------------------------
__global__ void edge_kernel(const int* __restrict__ src,
                            const int* __restrict__ seg) {
    const int idx  = blockIdx.x * blockDim.x + threadIdx.x;   // pack index
    const int lane = threadIdx.x & 31;

    float val = 0.f;
    int   key = -1;
    if (idx < N_EDGES / 4) {
        const int e0 = idx * 4;
        const int t  = e0 / E_PER_T;
        int4 s4 = reinterpret_cast<const int4*>(src)[idx];
        int4 g4 = reinterpret_cast<const int4*>(seg)[idx];

        float v0 = g_s[s4.x], v1 = g_s[s4.y], v2 = g_s[s4.z], v3 = g_s[s4.w];
        const int kb = t * BATCH;
        int k0 = kb + g4.x, k1 = kb + g4.y, k2 = kb + g4.z, k3 = kb + g4.w;

        // run compaction front-to-back; flush completed interior runs
        float acc = v0; int cur = k0;
        if (k1 == cur) acc += v1; else { atomicAdd(&g_acc[cur], acc); cur = k1; acc = v1; }
        if (k2 == cur) acc += v2; else { atomicAdd(&g_acc[cur], acc); cur = k2; acc = v2; }
        if (k3 == cur) acc += v3; else { atomicAdd(&g_acc[cur], acc); cur = k3; acc = v3; }
        val = acc; key = cur;   // carry tail run into warp stage
    }

    // segmented inclusive reduction over sorted tail-run keys
    #pragma unroll
    for (int off = 1; off < 32; off <<= 1) {
        int   okey = __shfl_down_sync(0xffffffffu, key, off);
        float oval = __shfl_down_sync(0xffffffffu, val, off);
        if (lane + off < 32 && okey == key) val += oval;
    }
    int pkey = __shfl_up_sync(0xffffffffu, key, 1);
    bool head = (lane == 0) || (pkey != key);
    if (head && key >= 0) atomicAdd(&g_acc[key], val);
}

// ---------------------------------------------------------------------------
// Kernel 3: mask + softmax. 36 threads per graph, 8 graphs per block (288
// threads), 32 blocks. Smem reductions — no register spills, full-chip spread.
// ---------------------------------------------------------------------------
__global__ void softmax_kernel(const int* __restrict__ mask,
                               float* __restrict__ out) {
    __shared__ float sv[8][N_ETYPES];
    __shared__ float sred[8];

    const int g = threadIdx.x / N_ETYPES;   // group 0..7
    const int t = threadIdx.x % N_ETYPES;   // type 0..35
    const int b = blockIdx.x * 8 + g;       // graph id

    float x = g_acc[t * BATCH + b];
    if (mask[b * N_ETYPES + t] != 0) x = -1e9f;
    sv[g][t] = x;
    __syncthreads();

    if (t == 0) {
        float mx = sv[g][0];
        #pragma unroll
        for (int i = 1; i < N_ETYPES; i++) mx = fmaxf(mx, sv[g][i]);
        sred[g] = mx;
    }
    __syncthreads();

    float e = __expf(x - sred[g]);
    sv[g][t] = e;
    __syncthreads();

    if (t == 0) {
        float s = 0.f;
        #pragma unroll
        for (int i = 0; i < N_ETYPES; i++) s += sv[g][i];
        sred[g] = s;
    }
    __syncthreads();

    out[b * N_ETYPES + t] = e / sred[g];
}

// ---------------------------------------------------------------------------
extern "C" void kernel_launch(void* const* d_in, const int* in_sizes, int n_in,
                              void* d_out, int out_size) {
    const float* h    = (const float*)d_in[0];   // [100000,192]
    const float* Wout = (const float*)d_in[1];   // [192,1]
    const int*   src  = (const int*)d_in[2];     // [36,30000]
    const int*   seg  = (const int*)d_in[3];     // [36,30000]
    const int*   mask = (const int*)d_in[4];     // [256,36] bool -> int32
    float*       out  = (float*)d_out;           // [256,36]

    dot_kernel<<<(N_BOND + 7) / 8, 256>>>(h, Wout);                 // + zeroing
    edge_kernel<<<(N_EDGES / 4 + 255) / 256, 256>>>(src, seg);
    softmax_kernel<<<BATCH / 8, 8 * N_ETYPES>>>(mask, out);
}

// round 4
// speedup vs baseline: 1.6622x; 1.2162x over previous
#include <cuda_runtime.h>
#include <cuda_bf16.h>

#define N_BOND   100000
#define D        192
#define N_ETYPES 36
#define E_PER_T  30000
#define BATCH    256
#define N_EDGES  (N_ETYPES * E_PER_T)   // 1,080,000
#define N_SEG    (N_ETYPES * BATCH)     // 9216

__device__ float g_s[N_BOND];     // per-node scalar projection h[i,:] . W_out
__device__ float g_acc[N_SEG];    // segment accumulators [type*BATCH + graph]

// ---------------------------------------------------------------------------
// Kernel 1: s[row] = dot(h[row,:], W_out).
// Half-warp per row, 4 rows per warp (2 unrolled iters), 6 LDG.128 in flight.
// Each LDG.128 serves two adjacent rows: lanes 0-15 -> row 2k, 16-31 -> 2k+1,
// both 256B dense. W (48 float4) lives in 3 regs/lane, loaded once.
// Also zeroes g_acc (fused; completes before edge_kernel launch).
// ---------------------------------------------------------------------------
__global__ void dot_kernel(const float* __restrict__ h,
                           const float* __restrict__ W) {
    const int tid = blockIdx.x * blockDim.x + threadIdx.x;
    if (tid < N_SEG) g_acc[tid] = 0.f;

    const int lane = threadIdx.x & 31;
    const int half = lane >> 4;           // 0 or 1
    const int hl   = lane & 15;           // lane within half-warp
    const int warp = tid >> 5;            // global warp id; rows 4w .. 4w+3

    const float4* W4 = reinterpret_cast<const float4*>(W);
    const float4 w0 = W4[hl];
    const float4 w1 = W4[16 + hl];
    const float4 w2 = W4[32 + hl];

    const int row0 = 4 * warp + half;     // iter 0 row
    const int row1 = row0 + 2;            // iter 1 row
    if (row1 >= N_BOND && row0 >= N_BOND) return;

    // Issue all 6 loads up front (independent -> max MLP)
    const float4* p0 = reinterpret_cast<const float4*>(h + (size_t)row0 * D);
    const float4* p1 = reinterpret_cast<const float4*>(h + (size_t)row1 * D);
    float4 a0 = p0[hl], b0 = p0[16 + hl], c0 = p0[32 + hl];
    float4 a1 = p1[hl], b1 = p1[16 + hl], c1 = p1[32 + hl];

    float acc0 = a0.x * w0.x + a0.y * w0.y + a0.z * w0.z + a0.w * w0.w
               + b0.x * w1.x + b0.y * w1.y + b0.z * w1.z + b0.w * w1.w
               + c0.x * w2.x + c0.y * w2.y + c0.z * w2.z + c0.w * w2.w;
    float acc1 = a1.x * w0.x + a1.y * w0.y + a1.z * w0.z + a1.w * w0.w
               + b1.x * w1.x + b1.y * w1.y + b1.z * w1.z + b1.w * w1.w
               + c1.x * w2.x + c1.y * w2.y + c1.z * w2.z + c1.w * w2.w;

    // Width-16 reductions (two independent chains interleave in the pipe)
    #pragma unroll
    for (int off = 8; off > 0; off >>= 1) {
        acc0 += __shfl_down_sync(0xffffffffu, acc0, off, 16);
        acc1 += __shfl_down_sync(0xffffffffu, acc1, off, 16);
    }
    if (hl == 0) {
        g_s[row0] = acc0;
        g_s[row1] = acc1;
    }
}

// ---------------------------------------------------------------------------
// Kernel 2: 4 edges per thread (int4), intra-thread run compaction, then
// warp-level segmented reduction over sorted keys, atomicAdd per run head.
// ---------------------------------------------------------------------------
__global__ void edge_kernel(const int* __restrict__ src,
                            const int* __restrict__ seg) {
    const int idx  = blockIdx.x * blockDim.x + threadIdx.x;   // pack index
    const int lane = threadIdx.x & 31;

    float val = 0.f;
    int   key = -1;
    if (idx < N_EDGES / 4) {
        const int e0 = idx * 4;
        const int t  = e0 / E_PER_T;
        int4 s4 = reinterpret_cast<const int4*>(src)[idx];
        int4 g4 = reinterpret_cast<const int4*>(seg)[idx];

        float v0 = g_s[s4.x], v1 = g_s[s4.y], v2 = g_s[s4.z], v3 = g_s[s4.w];
        const int kb = t * BATCH;
        int k0 = kb + g4.x, k1 = kb + g4.y, k2 = kb + g4.z, k3 = kb + g4.w;

        float acc = v0; int cur = k0;
        if (k1 == cur) acc += v1; else { atomicAdd(&g_acc[cur], acc); cur = k1; acc = v1; }
        if (k2 == cur) acc += v2; else { atomicAdd(&g_acc[cur], acc); cur = k2; acc = v2; }
        if (k3 == cur) acc += v3; else { atomicAdd(&g_acc[cur], acc); cur = k3; acc = v3; }
        val = acc; key = cur;   // tail run into warp stage
    }

    #pragma unroll
    for (int off = 1; off < 32; off <<= 1) {
        int   okey = __shfl_down_sync(0xffffffffu, key, off);
        float oval = __shfl_down_sync(0xffffffffu, val, off);
        if (lane + off < 32 && okey == key) val += oval;
    }
    int pkey = __shfl_up_sync(0xffffffffu, key, 1);
    bool head = (lane == 0) || (pkey != key);
    if (head && key >= 0) atomicAdd(&g_acc[key], val);
}

// ---------------------------------------------------------------------------
// Kernel 3: mask + softmax. 36 threads/graph, 8 graphs/block, 32 blocks.
// ---------------------------------------------------------------------------
__global__ void softmax_kernel(const int* __restrict__ mask,
                               float* __restrict__ out) {
    __shared__ float sv[8][N_ETYPES];
    __shared__ float sred[8];

    const int g = threadIdx.x / N_ETYPES;
    const int t = threadIdx.x % N_ETYPES;
    const int b = blockIdx.x * 8 + g;

    float x = g_acc[t * BATCH + b];
    if (mask[b * N_ETYPES + t] != 0) x = -1e9f;
    sv[g][t] = x;
    __syncthreads();

    if (t == 0) {
        float mx = sv[g][0];
        #pragma unroll
        for (int i = 1; i < N_ETYPES; i++) mx = fmaxf(mx, sv[g][i]);
        sred[g] = mx;
    }
    __syncthreads();

    float e = __expf(x - sred[g]);
    sv[g][t] = e;
    __syncthreads();

    if (t == 0) {
        float s = 0.f;
        #pragma unroll
        for (int i = 0; i < N_ETYPES; i++) s += sv[g][i];
        sred[g] = s;
    }
    __syncthreads();

    out[b * N_ETYPES + t] = e / sred[g];
}

// ---------------------------------------------------------------------------
extern "C" void kernel_launch(void* const* d_in, const int* in_sizes, int n_in,
                              void* d_out, int out_size) {
    const float* h    = (const float*)d_in[0];   // [100000,192]
    const float* Wout = (const float*)d_in[1];   // [192,1]
    const int*   src  = (const int*)d_in[2];     // [36,30000]
    const int*   seg  = (const int*)d_in[3];     // [36,30000]
    const int*   mask = (const int*)d_in[4];     // [256,36] bool -> int32
    float*       out  = (float*)d_out;           // [256,36]

    // 4 rows per warp, 8 warps per block -> 32 rows per block
    dot_kernel<<<(N_BOND + 31) / 32, 256>>>(h, Wout);          // + g_acc zeroing
    edge_kernel<<<(N_EDGES / 4 + 255) / 256, 256>>>(src, seg);
    softmax_kernel<<<BATCH / 8, 8 * N_ETYPES>>>(mask, out);
}